// round 1
// baseline (speedup 1.0000x reference)
#include <cuda_runtime.h>
#include <mma.h>

using namespace nvcuda;

// Problem constants
#define M_ENS 8
#define BATCH 4096
#define OBS_D 64
#define ACT_D 32
#define IN_D  96          // OBS+ACT
#define H_D   1024
#define HEAD_NP 192       // padded head output columns (130 real -> 192)

// d_out layout (tuple flattened): mu_o[M,B,OBS], log_var_o[M,B,OBS], mu_r[M,B,1], log_var_r[M,B,1]
#define OFF_LV_O  (M_ENS * BATCH * OBS_D)            // 2097152
#define OFF_MU_R  (2 * M_ENS * BATCH * OBS_D)        // 4194304
#define OFF_LV_R  (OFF_MU_R + M_ENS * BATCH)         // 4227072

// ---- Scratch (static device allocations; no cudaMalloc allowed) ----
__device__ float g_x[BATCH * IN_D];                                  // 1.5 MB
__device__ float g_h0[(size_t)M_ENS * BATCH * H_D];                  // 134 MB
__device__ float g_h1[(size_t)M_ENS * BATCH * H_D];                  // 134 MB
__device__ float g_wh[(size_t)M_ENS * H_D * HEAD_NP];                // 6.3 MB
__device__ float g_bh[M_ENS * HEAD_NP];

// ---------------------------------------------------------------------------
__global__ void concat_kernel(const float* __restrict__ obs,
                              const float* __restrict__ act,
                              float* __restrict__ x) {
    int idx = blockIdx.x * blockDim.x + threadIdx.x;
    if (idx >= BATCH * IN_D) return;
    int b = idx / IN_D, i = idx - b * IN_D;
    x[idx] = (i < OBS_D) ? obs[b * OBS_D + i] : act[b * ACT_D + (i - OBS_D)];
}

// Pack the four head weight tensors into a single [M, H, HEAD_NP] GEMM operand.
// col n: [0,64) mu_o | 64 mu_r | [65,129) v_o | 129 v_r | [130,192) zero
__global__ void pack_heads_kernel(const float* __restrict__ Wmu_o,
                                  const float* __restrict__ Wmu_r,
                                  const float* __restrict__ Wv_o,
                                  const float* __restrict__ Wv_r,
                                  const float* __restrict__ bmu_o,
                                  const float* __restrict__ bmu_r,
                                  const float* __restrict__ bv_o,
                                  const float* __restrict__ bv_r,
                                  float* __restrict__ wh,
                                  float* __restrict__ bh) {
    int idx = blockIdx.x * blockDim.x + threadIdx.x;
    int total = M_ENS * H_D * HEAD_NP;
    if (idx < total) {
        int m = idx / (H_D * HEAD_NP);
        int rem = idx - m * (H_D * HEAD_NP);
        int k = rem / HEAD_NP;
        int n = rem - k * HEAD_NP;
        float v = 0.f;
        size_t mk = (size_t)m * H_D + k;
        if (n < OBS_D)        v = Wmu_o[mk * OBS_D + n];
        else if (n == OBS_D)  v = Wmu_r[mk];
        else if (n < 129)     v = Wv_o[mk * OBS_D + (n - 65)];
        else if (n == 129)    v = Wv_r[mk];
        wh[idx] = v;
    }
    if (idx < M_ENS * HEAD_NP) {
        int m = idx / HEAD_NP, n = idx - m * HEAD_NP;
        float v = 0.f;
        if (n < OBS_D)        v = bmu_o[m * OBS_D + n];
        else if (n == OBS_D)  v = bmu_r[m];
        else if (n < 129)     v = bv_o[m * OBS_D + (n - 65)];
        else if (n == 129)    v = bv_r[m];
        bh[idx] = v;
    }
}

// ---------------------------------------------------------------------------
__device__ __forceinline__ float softplusf(float x) {
    return fmaxf(x, 0.f) + log1pf(expf(-fabsf(x)));
}
__device__ __forceinline__ float clamp_log_var(float v) {
    v = 0.5f  - softplusf(0.5f - v);
    v = -10.f + softplusf(v + 10.f);
    return v;
}

// Tiled tf32 GEMM: C[m] = act(A[m] (BATCH x K) @ W[m] (K x N) + bias[m])
// BM=128, BN=64, BK=32, 256 threads (8 warps as 4x2 of 32x32 warp tiles).
template <int KTOT, bool HEADS>
__global__ __launch_bounds__(256)
void gemm_tf32(const float* __restrict__ A, size_t strideAm,
               const float* __restrict__ W, size_t strideWm,
               const float* __restrict__ bias, size_t strideBm,
               int ldA, int ldW,
               float* __restrict__ out, size_t strideOm, int ldO) {
    const int m   = blockIdx.z;
    const int bm0 = blockIdx.x * 128;
    const int bn0 = blockIdx.y * 64;
    const int tid = threadIdx.x;
    const int wid = tid >> 5;
    const int wm  = wid & 3;   // warp row (M)
    const int wn  = wid >> 2;  // warp col (N)

    __shared__ __align__(16) union Smem {
        struct { float As[128][36]; float Bs[32][68]; } in;
        float Cs[128][68];
    } sm;

    const float* Am = A + strideAm * m;
    const float* Wm = W + strideWm * m;

    wmma::fragment<wmma::accumulator, 16, 16, 8, float> acc[2][2];
#pragma unroll
    for (int i = 0; i < 2; i++)
#pragma unroll
        for (int j = 0; j < 2; j++) wmma::fill_fragment(acc[i][j], 0.f);

    for (int k0 = 0; k0 < KTOT; k0 += 32) {
        // A tile: 128x32 (1024 float4, 4 per thread)
#pragma unroll
        for (int p = 0; p < 4; p++) {
            int f = tid + p * 256;
            int r = f >> 3, cv = f & 7;
            const float4 v = *reinterpret_cast<const float4*>(
                Am + (size_t)(bm0 + r) * ldA + k0 + cv * 4);
            float* d = &sm.in.As[r][cv * 4];
            d[0] = wmma::__float_to_tf32(v.x);
            d[1] = wmma::__float_to_tf32(v.y);
            d[2] = wmma::__float_to_tf32(v.z);
            d[3] = wmma::__float_to_tf32(v.w);
        }
        // W tile: 32x64 (512 float4, 2 per thread)
#pragma unroll
        for (int p = 0; p < 2; p++) {
            int f = tid + p * 256;
            int r = f >> 4, cv = f & 15;
            const float4 v = *reinterpret_cast<const float4*>(
                Wm + (size_t)(k0 + r) * ldW + bn0 + cv * 4);
            float* d = &sm.in.Bs[r][cv * 4];
            d[0] = wmma::__float_to_tf32(v.x);
            d[1] = wmma::__float_to_tf32(v.y);
            d[2] = wmma::__float_to_tf32(v.z);
            d[3] = wmma::__float_to_tf32(v.w);
        }
        __syncthreads();
#pragma unroll
        for (int kk = 0; kk < 32; kk += 8) {
            wmma::fragment<wmma::matrix_a, 16, 16, 8, wmma::precision::tf32,
                           wmma::row_major> afrag[2];
            wmma::fragment<wmma::matrix_b, 16, 16, 8, wmma::precision::tf32,
                           wmma::row_major> bfrag[2];
#pragma unroll
            for (int i = 0; i < 2; i++)
                wmma::load_matrix_sync(afrag[i], &sm.in.As[wm * 32 + i * 16][kk], 36);
#pragma unroll
            for (int j = 0; j < 2; j++)
                wmma::load_matrix_sync(bfrag[j], &sm.in.Bs[kk][wn * 32 + j * 16], 68);
#pragma unroll
            for (int i = 0; i < 2; i++)
#pragma unroll
                for (int j = 0; j < 2; j++)
                    wmma::mma_sync(acc[i][j], afrag[i], bfrag[j], acc[i][j]);
        }
        __syncthreads();
    }

    // Stage accumulators through smem for a layout-agnostic epilogue.
#pragma unroll
    for (int i = 0; i < 2; i++)
#pragma unroll
        for (int j = 0; j < 2; j++)
            wmma::store_matrix_sync(&sm.Cs[wm * 32 + i * 16][wn * 32 + j * 16],
                                    acc[i][j], 68, wmma::mem_row_major);
    __syncthreads();

    const float* bm_ = bias + strideBm * m;
    if (!HEADS) {
        float* om = out + strideOm * m;
        for (int idx = tid; idx < 128 * 64; idx += 256) {
            int r = idx >> 6, c = idx & 63;
            float v = sm.Cs[r][c] + bm_[bn0 + c];
            om[(size_t)(bm0 + r) * ldO + bn0 + c] = tanhf(v);
        }
    } else {
        for (int idx = tid; idx < 128 * 64; idx += 256) {
            int r = idx >> 6, c = idx & 63;
            int gc = bn0 + c;
            if (gc >= 130) continue;
            int gr = bm0 + r;
            float v = sm.Cs[r][c] + bm_[gc];
            if (gc < OBS_D) {
                out[((size_t)m * BATCH + gr) * OBS_D + gc] = v;           // mu_o
            } else if (gc == OBS_D) {
                out[OFF_MU_R + (size_t)m * BATCH + gr] = v;               // mu_r
            } else if (gc < 129) {
                out[OFF_LV_O + ((size_t)m * BATCH + gr) * OBS_D + (gc - 65)] =
                    clamp_log_var(v);                                     // log_var_o
            } else {
                out[OFF_LV_R + (size_t)m * BATCH + gr] = clamp_log_var(v); // log_var_r
            }
        }
    }
}

// ---------------------------------------------------------------------------
extern "C" void kernel_launch(void* const* d_in, const int* in_sizes, int n_in,
                              void* d_out, int out_size) {
    const float* obs   = (const float*)d_in[0];
    const float* act   = (const float*)d_in[1];
    const float* W0    = (const float*)d_in[2];
    const float* b0    = (const float*)d_in[3];
    const float* W1    = (const float*)d_in[4];
    const float* b1    = (const float*)d_in[5];
    const float* W2    = (const float*)d_in[6];
    const float* b2    = (const float*)d_in[7];
    const float* Wmu_o = (const float*)d_in[8];
    const float* bmu_o = (const float*)d_in[9];
    const float* Wmu_r = (const float*)d_in[10];
    const float* bmu_r = (const float*)d_in[11];
    const float* Wv_o  = (const float*)d_in[12];
    const float* bv_o  = (const float*)d_in[13];
    const float* Wv_r  = (const float*)d_in[14];
    const float* bv_r  = (const float*)d_in[15];
    float* out = (float*)d_out;

    float *px, *ph0, *ph1, *pwh, *pbh;
    cudaGetSymbolAddress((void**)&px,  g_x);
    cudaGetSymbolAddress((void**)&ph0, g_h0);
    cudaGetSymbolAddress((void**)&ph1, g_h1);
    cudaGetSymbolAddress((void**)&pwh, g_wh);
    cudaGetSymbolAddress((void**)&pbh, g_bh);

    concat_kernel<<<(BATCH * IN_D + 255) / 256, 256>>>(obs, act, px);
    pack_heads_kernel<<<(M_ENS * H_D * HEAD_NP + 255) / 256, 256>>>(
        Wmu_o, Wmu_r, Wv_o, Wv_r, bmu_o, bmu_r, bv_o, bv_r, pwh, pbh);

    const size_t sHM = (size_t)BATCH * H_D;        // activation per-ensemble stride
    dim3 gridH(BATCH / 128, H_D / 64, M_ENS);      // (32,16,8)

    // layer 0: h0 = tanh(x @ W0 + b0)   (A shared across ensembles)
    gemm_tf32<IN_D, false><<<gridH, 256>>>(px, 0, W0, (size_t)IN_D * H_D,
                                           b0, H_D, IN_D, H_D,
                                           ph0, sHM, H_D);
    // layer 1: h1 = tanh(h0 @ W1 + b1)
    gemm_tf32<H_D, false><<<gridH, 256>>>(ph0, sHM, W1, (size_t)H_D * H_D,
                                          b1, H_D, H_D, H_D,
                                          ph1, sHM, H_D);
    // layer 2: h0 = tanh(h1 @ W2 + b2)
    gemm_tf32<H_D, false><<<gridH, 256>>>(ph1, sHM, W2, (size_t)H_D * H_D,
                                          b2, H_D, H_D, H_D,
                                          ph0, sHM, H_D);
    // heads: packed [K=1024, N=192] GEMM with scatter + log-var clamp epilogue
    dim3 gridHead(BATCH / 128, HEAD_NP / 64, M_ENS);  // (32,3,8)
    gemm_tf32<H_D, true><<<gridHead, 256>>>(ph0, sHM, pwh, (size_t)H_D * HEAD_NP,
                                            pbh, HEAD_NP, H_D, HEAD_NP,
                                            out, 0, 0);
}

// round 3
// speedup vs baseline: 2.4793x; 2.4793x over previous
#include <cuda_runtime.h>
#include <cstdint>

// ---------------- Problem constants ----------------
#define M_ENS 8
#define BATCH 4096
#define OBS_D 64
#define IN_D  96
#define H_D   1024
#define HEAD_N 192    // packed head cols (130 real, padded)

#define OFF_LV_O  (M_ENS * BATCH * OBS_D)
#define OFF_MU_R  (2 * M_ENS * BATCH * OBS_D)
#define OFF_LV_R  (OFF_MU_R + M_ENS * BATCH)

// ---------------- Scratch (static device memory) ----------------
__device__ __align__(256) float g_x[BATCH * IN_D];
__device__ __align__(256) float g_h0[(size_t)M_ENS * BATCH * H_D];
__device__ __align__(256) float g_h1[(size_t)M_ENS * BATCH * H_D];
__device__ __align__(256) float g_wt0[(size_t)M_ENS * H_D * IN_D];   // [m][n][k]
__device__ __align__(256) float g_wt1[(size_t)M_ENS * H_D * H_D];
__device__ __align__(256) float g_wt2[(size_t)M_ENS * H_D * H_D];
__device__ __align__(256) float g_wth[(size_t)M_ENS * HEAD_N * H_D]; // [m][n][k]
__device__ __align__(256) float g_bh[M_ENS * HEAD_N];

// ---------------- helpers ----------------
__device__ __forceinline__ uint32_t smem_u32(const void* p) {
    uint32_t a;
    asm("{ .reg .u64 t; cvta.to.shared.u64 t, %1; cvt.u32.u64 %0, t; }" : "=r"(a) : "l"(p));
    return a;
}
__device__ __forceinline__ float tf32r(float x) {
    uint32_t u;
    asm("cvt.rna.tf32.f32 %0, %1;" : "=r"(u) : "f"(x));
    return __uint_as_float(u);
}
#define CPA(dst, src)  asm volatile("cp.async.cg.shared.global [%0], [%1], 16;" :: "r"(dst), "l"(src))
#define CPA_COMMIT()   asm volatile("cp.async.commit_group;" ::: "memory")
template <int N>
__device__ __forceinline__ void cpa_wait() {
    asm volatile("cp.async.wait_group %0;" :: "n"(N) : "memory");
}

__device__ __forceinline__ void mma_tf32(float* c, const uint32_t* a, const uint32_t* b) {
    asm volatile(
        "mma.sync.aligned.m16n8k8.row.col.f32.tf32.tf32.f32 "
        "{%0,%1,%2,%3}, {%4,%5,%6,%7}, {%8,%9}, {%0,%1,%2,%3};"
        : "+f"(c[0]), "+f"(c[1]), "+f"(c[2]), "+f"(c[3])
        : "r"(a[0]), "r"(a[1]), "r"(a[2]), "r"(a[3]), "r"(b[0]), "r"(b[1]));
}

__device__ __forceinline__ float softplusf(float x) {
    return fmaxf(x, 0.f) + log1pf(expf(-fabsf(x)));
}
__device__ __forceinline__ float clampv(float v) {
    v = 0.5f  - softplusf(0.5f - v);
    v = -10.f + softplusf(v + 10.f);
    return v;
}

// ---------------- Prep kernels ----------------
__global__ void concat_round(const float* __restrict__ obs,
                             const float* __restrict__ act,
                             float* __restrict__ x) {
    int idx = blockIdx.x * blockDim.x + threadIdx.x;
    if (idx >= BATCH * IN_D) return;
    int b = idx / IN_D, i = idx - b * IN_D;
    float v = (i < OBS_D) ? obs[b * OBS_D + i] : act[b * 32 + (i - OBS_D)];
    x[idx] = tf32r(v);
}

// src [m][K][N] -> dst [m][N][K], rounded to tf32
__global__ void transpose_round(const float* __restrict__ src,
                                float* __restrict__ dst, int K, int N) {
    __shared__ float t[32][33];
    int m = blockIdx.z;
    int k0 = blockIdx.x * 32, n0 = blockIdx.y * 32;
    const float* s = src + (size_t)m * K * N;
    float* d = dst + (size_t)m * K * N;
    int tx = threadIdx.x, ty = threadIdx.y;
#pragma unroll
    for (int dy = 0; dy < 32; dy += 8)
        t[ty + dy][tx] = s[(size_t)(k0 + ty + dy) * N + n0 + tx];
    __syncthreads();
#pragma unroll
    for (int dy = 0; dy < 32; dy += 8)
        d[(size_t)(n0 + ty + dy) * K + k0 + tx] = tf32r(t[tx][ty + dy]);
}

// Pack heads transposed: wth[m][n][k]
__global__ void pack_heads(const float* __restrict__ Wmu_o, const float* __restrict__ Wmu_r,
                           const float* __restrict__ Wv_o,  const float* __restrict__ Wv_r,
                           const float* __restrict__ bmu_o, const float* __restrict__ bmu_r,
                           const float* __restrict__ bv_o,  const float* __restrict__ bv_r,
                           float* __restrict__ wth, float* __restrict__ bh) {
    int idx = blockIdx.x * blockDim.x + threadIdx.x;
    int total = M_ENS * HEAD_N * H_D;
    if (idx < total) {
        int m = idx / (HEAD_N * H_D);
        int rem = idx - m * (HEAD_N * H_D);
        int n = rem / H_D;
        int k = rem - n * H_D;
        size_t mk = (size_t)m * H_D + k;
        float v = 0.f;
        if (n < 64)        v = Wmu_o[mk * 64 + n];
        else if (n == 64)  v = Wmu_r[mk];
        else if (n < 129)  v = Wv_o[mk * 64 + (n - 65)];
        else if (n == 129) v = Wv_r[mk];
        wth[idx] = tf32r(v);
    }
    if (idx < M_ENS * HEAD_N) {
        int m = idx / HEAD_N, n = idx - m * HEAD_N;
        float v = 0.f;
        if (n < 64)        v = bmu_o[m * 64 + n];
        else if (n == 64)  v = bmu_r[m];
        else if (n < 129)  v = bv_o[m * 64 + n - 65];
        else if (n == 129) v = bv_r[m];
        bh[idx] = v;
    }
}

// ---------------- tf32 mma.sync GEMM ----------------
// C[m] (128 x BN tile) = A[m][row][k] @ Wt[m][col][k]^T  (+bias, +act)
// 256 threads, 8 warps. Warp tile WM x WN. 3-stage cp.async pipeline, BK=32.
// Smem: per stage, A[128][36] then B[BN][36] (K-major rows, pad 4).
template <int KTOT, int BN, int WM, int WN, bool HEADS>
__global__ __launch_bounds__(256)
void gemm_mma(const float* __restrict__ A, size_t sAm, int ldA,
              const float* __restrict__ Wt, size_t sWm,
              const float* __restrict__ bias, int sBm,
              float* __restrict__ out, size_t sOm, int ldO) {
    constexpr int NKB = KTOT / 32;
    constexpr int WARPS_M = 128 / WM;
    constexpr int MT = WM / 16;
    constexpr int NT = WN / 8;
    constexpr int STAGE_F = (128 + BN) * 36;          // floats per stage
    constexpr int A_NB4 = 128 * 8 / 256;              // float4s per thread for A
    constexpr int B_NB4 = BN * 8 / 256;

    extern __shared__ float smem[];
    const uint32_t sb = smem_u32(smem);
    const int tid = threadIdx.x;
    const int wid = tid >> 5, lane = tid & 31;
    const int wm = wid % WARPS_M, wn = wid / WARPS_M;
    const int gq = lane >> 2, tq = lane & 3;          // group, thread-in-group
    const int m = blockIdx.z;
    const int bm0 = blockIdx.x * 128;
    const int bn0 = blockIdx.y * BN;

    const float* Am  = A + sAm * m;
    const float* Wm  = Wt + sWm * m;
    const float* bm_ = bias + (size_t)sBm * m;

    auto fill = [&](int s, int kb) {
        uint32_t abase = sb + s * STAGE_F * 4;
#pragma unroll
        for (int p = 0; p < A_NB4; p++) {
            int f = tid + p * 256;
            int r = f >> 3, cv = f & 7;
            CPA(abase + r * 144 + cv * 16,
                Am + (size_t)(bm0 + r) * ldA + kb * 32 + cv * 4);
        }
        uint32_t bbase = abase + 128 * 144;
#pragma unroll
        for (int p = 0; p < B_NB4; p++) {
            int f = tid + p * 256;
            int r = f >> 3, cv = f & 7;
            CPA(bbase + r * 144 + cv * 16,
                Wm + (size_t)(bn0 + r) * KTOT + kb * 32 + cv * 4);
        }
        CPA_COMMIT();
    };

    float acc[MT][NT][4];
#pragma unroll
    for (int i = 0; i < MT; i++)
#pragma unroll
        for (int j = 0; j < NT; j++)
#pragma unroll
            for (int q = 0; q < 4; q++) acc[i][j][q] = 0.f;

    fill(0, 0);
    fill(1, 1);

    for (int kb = 0; kb < NKB; kb++) {
        if (kb == NKB - 1) cpa_wait<0>(); else cpa_wait<1>();
        __syncthreads();
        if (kb + 2 < NKB) fill((kb + 2) % 3, kb + 2);

        const uint32_t* As = (const uint32_t*)(smem + (kb % 3) * STAGE_F);
        const uint32_t* Bs = As + 128 * 36;
#pragma unroll
        for (int kk = 0; kk < 4; kk++) {
            uint32_t afr[MT][4], bfr[NT][2];
#pragma unroll
            for (int mt = 0; mt < MT; mt++) {
                int r = wm * WM + mt * 16 + gq;
                int c = kk * 8 + tq;
                afr[mt][0] = As[r * 36 + c];
                afr[mt][1] = As[(r + 8) * 36 + c];
                afr[mt][2] = As[r * 36 + c + 4];
                afr[mt][3] = As[(r + 8) * 36 + c + 4];
            }
#pragma unroll
            for (int nt = 0; nt < NT; nt++) {
                int rn = wn * WN + nt * 8 + gq;
                int c = kk * 8 + tq;
                bfr[nt][0] = Bs[rn * 36 + c];
                bfr[nt][1] = Bs[rn * 36 + c + 4];
            }
#pragma unroll
            for (int mt = 0; mt < MT; mt++)
#pragma unroll
                for (int nt = 0; nt < NT; nt++)
                    mma_tf32(acc[mt][nt], afr[mt], bfr[nt]);
        }
    }

    // ---- epilogue (register -> gmem) ----
    // c0:(row=gq, col=2*tq) c1:+1col c2:+8row c3:+8row+1col
    if (!HEADS) {
        float* om = out + sOm * m;
#pragma unroll
        for (int nt = 0; nt < NT; nt++) {
            int gc = bn0 + wn * WN + nt * 8 + tq * 2;
            float bA = bm_[gc], bB = bm_[gc + 1];
#pragma unroll
            for (int mt = 0; mt < MT; mt++) {
                int gr = bm0 + wm * WM + mt * 16 + gq;
                float2 v0, v1;
                v0.x = tf32r(tanhf(acc[mt][nt][0] + bA));
                v0.y = tf32r(tanhf(acc[mt][nt][1] + bB));
                v1.x = tf32r(tanhf(acc[mt][nt][2] + bA));
                v1.y = tf32r(tanhf(acc[mt][nt][3] + bB));
                *(float2*)(om + (size_t)gr * ldO + gc) = v0;
                *(float2*)(om + (size_t)(gr + 8) * ldO + gc) = v1;
            }
        }
    } else {
#pragma unroll
        for (int nt = 0; nt < NT; nt++) {
#pragma unroll
            for (int q2 = 0; q2 < 2; q2++) {
                int gc = bn0 + wn * WN + nt * 8 + tq * 2 + q2;
                if (gc >= 130) continue;
                float bb = bm_[gc];
#pragma unroll
                for (int mt = 0; mt < MT; mt++) {
#pragma unroll
                    for (int h = 0; h < 2; h++) {
                        int gr = bm0 + wm * WM + mt * 16 + gq + h * 8;
                        float v = acc[mt][nt][h * 2 + q2] + bb;
                        if (gc < 64)
                            out[((size_t)m * BATCH + gr) * 64 + gc] = v;
                        else if (gc == 64)
                            out[OFF_MU_R + (size_t)m * BATCH + gr] = v;
                        else if (gc < 129)
                            out[OFF_LV_O + ((size_t)m * BATCH + gr) * 64 + (gc - 65)] = clampv(v);
                        else
                            out[OFF_LV_R + (size_t)m * BATCH + gr] = clampv(v);
                    }
                }
            }
        }
    }
}

// ---------------- Launch ----------------
extern "C" void kernel_launch(void* const* d_in, const int* in_sizes, int n_in,
                              void* d_out, int out_size) {
    const float* obs   = (const float*)d_in[0];
    const float* act   = (const float*)d_in[1];
    const float* W0    = (const float*)d_in[2];
    const float* b0    = (const float*)d_in[3];
    const float* W1    = (const float*)d_in[4];
    const float* b1    = (const float*)d_in[5];
    const float* W2    = (const float*)d_in[6];
    const float* b2    = (const float*)d_in[7];
    const float* Wmu_o = (const float*)d_in[8];
    const float* bmu_o = (const float*)d_in[9];
    const float* Wmu_r = (const float*)d_in[10];
    const float* bmu_r = (const float*)d_in[11];
    const float* Wv_o  = (const float*)d_in[12];
    const float* bv_o  = (const float*)d_in[13];
    const float* Wv_r  = (const float*)d_in[14];
    const float* bv_r  = (const float*)d_in[15];
    float* out = (float*)d_out;

    float *px, *ph0, *ph1, *pwt0, *pwt1, *pwt2, *pwth, *pbh;
    cudaGetSymbolAddress((void**)&px,   g_x);
    cudaGetSymbolAddress((void**)&ph0,  g_h0);
    cudaGetSymbolAddress((void**)&ph1,  g_h1);
    cudaGetSymbolAddress((void**)&pwt0, g_wt0);
    cudaGetSymbolAddress((void**)&pwt1, g_wt1);
    cudaGetSymbolAddress((void**)&pwt2, g_wt2);
    cudaGetSymbolAddress((void**)&pwth, g_wth);
    cudaGetSymbolAddress((void**)&pbh,  g_bh);

    // Layers: BN=128, warp tile 64x32.  Heads: BN=64, warp tile 32x32.
    const int SM_L = 3 * (128 + 128) * 36 * 4;   // 110592 B
    const int SM_H = 3 * (128 + 64) * 36 * 4;    //  82944 B
    cudaFuncSetAttribute((const void*)gemm_mma<IN_D, 128, 64, 32, false>,
                         cudaFuncAttributeMaxDynamicSharedMemorySize, SM_L);
    cudaFuncSetAttribute((const void*)gemm_mma<H_D, 128, 64, 32, false>,
                         cudaFuncAttributeMaxDynamicSharedMemorySize, SM_L);
    cudaFuncSetAttribute((const void*)gemm_mma<H_D, 64, 32, 32, true>,
                         cudaFuncAttributeMaxDynamicSharedMemorySize, SM_H);

    // prep
    concat_round<<<(BATCH * IN_D + 255) / 256, 256>>>(obs, act, px);
    transpose_round<<<dim3(IN_D / 32, H_D / 32, M_ENS), dim3(32, 8)>>>(W0, pwt0, IN_D, H_D);
    transpose_round<<<dim3(H_D / 32, H_D / 32, M_ENS), dim3(32, 8)>>>(W1, pwt1, H_D, H_D);
    transpose_round<<<dim3(H_D / 32, H_D / 32, M_ENS), dim3(32, 8)>>>(W2, pwt2, H_D, H_D);
    pack_heads<<<(M_ENS * HEAD_N * H_D + 255) / 256, 256>>>(
        Wmu_o, Wmu_r, Wv_o, Wv_r, bmu_o, bmu_r, bv_o, bv_r, pwth, pbh);

    const size_t sH = (size_t)BATCH * H_D;
    dim3 gridL(BATCH / 128, H_D / 128, M_ENS);      // (32,8,8)

    gemm_mma<IN_D, 128, 64, 32, false><<<gridL, 256, SM_L>>>(
        px, 0, IN_D, pwt0, (size_t)H_D * IN_D, b0, H_D, ph0, sH, H_D);
    gemm_mma<H_D, 128, 64, 32, false><<<gridL, 256, SM_L>>>(
        ph0, sH, H_D, pwt1, (size_t)H_D * H_D, b1, H_D, ph1, sH, H_D);
    gemm_mma<H_D, 128, 64, 32, false><<<gridL, 256, SM_L>>>(
        ph1, sH, H_D, pwt2, (size_t)H_D * H_D, b2, H_D, ph0, sH, H_D);

    dim3 gridH(BATCH / 128, HEAD_N / 64, M_ENS);    // (32,3,8)
    gemm_mma<H_D, 64, 32, 32, true><<<gridH, 256, SM_H>>>(
        ph0, sH, H_D, pwth, (size_t)HEAD_N * H_D, pbh, HEAD_N, out, 0, 0);
}